// round 1
// baseline (speedup 1.0000x reference)
#include <cuda_runtime.h>
#include <cuda_bf16.h>
#include <math.h>

// Problem constants
#define NN     20000
#define EE     320000
#define RNA    2000
#define PROT   100
#define EMB    256
#define HID    128
#define NHEAD  4
#define HD     512            // HID * NHEAD
#define INF    2100           // RNA + PROT
#define NEG_SLOPE 0.2f

// ---------------------------------------------------------------------------
// Scratch (device globals; no dynamic allocation allowed)
// ---------------------------------------------------------------------------
__device__ __align__(16) float g_h0[(size_t)NN * HD];
__device__ __align__(16) float g_h1[(size_t)NN * HD];
__device__ __align__(16) float g_xs[(size_t)NN * HD];
__device__ __align__(16) float g_xd[(size_t)NN * HD];
__device__ __align__(16) float g_lin[(size_t)NN * HD];
__device__ __align__(16) float g_asrc[(size_t)NN * NHEAD];
__device__ __align__(16) float g_adst[(size_t)NN * NHEAD];
__device__ int g_deg[NN];
__device__ int g_cursor[NN];
__device__ int g_rowptr[NN + 1];
__device__ int g_csr[EE];

// ---------------------------------------------------------------------------
// Generic fp32 SGEMM: C[M,N] = A[M,K](lda) @ B[K,N](ldb) (+bias1 +bias2)(+relu)
// 128x128x16 tiles, 8x8 per thread, 256 threads.
// ---------------------------------------------------------------------------
#define TM 128
#define TN 128
#define TK 16

__global__ void __launch_bounds__(256)
sgemm_kernel(const float* __restrict__ A, int lda,
             const float* __restrict__ B, int ldb,
             float* __restrict__ C, int ldc,
             int M, int N, int K,
             const float* __restrict__ bias1,
             const float* __restrict__ bias2,
             int do_relu)
{
    __shared__ float As[TK][TM + 4];
    __shared__ float Bs[TK][TN];

    const int tid = threadIdx.x;
    const int tx = tid & 15;       // 0..15  -> col group
    const int ty = tid >> 4;       // 0..15  -> row group
    const int row0 = blockIdx.y * TM;
    const int col0 = blockIdx.x * TN;

    float acc[8][8];
#pragma unroll
    for (int i = 0; i < 8; i++)
#pragma unroll
        for (int j = 0; j < 8; j++) acc[i][j] = 0.f;

    for (int k0 = 0; k0 < K; k0 += TK) {
        // Load A tile (TM x TK): idx -> k = idx%16, m = idx/16 (coalesced-ish rows)
#pragma unroll
        for (int i = 0; i < 8; i++) {
            int idx = tid + i * 256;
            int k = idx & 15;
            int m = idx >> 4;
            int gr = row0 + m, gk = k0 + k;
            float v = 0.f;
            if (gr < M && gk < K) v = A[(size_t)gr * lda + gk];
            As[k][m] = v;
        }
        // Load B tile (TK x TN): idx -> n = idx%128, k = idx/128 (coalesced)
#pragma unroll
        for (int i = 0; i < 8; i++) {
            int idx = tid + i * 256;
            int n = idx & 127;
            int k = idx >> 7;
            int gk = k0 + k, gc = col0 + n;
            float v = 0.f;
            if (gk < K && gc < N) v = B[(size_t)gk * ldb + gc];
            Bs[k][n] = v;
        }
        __syncthreads();

#pragma unroll
        for (int k = 0; k < TK; k++) {
            float a[8], b[8];
#pragma unroll
            for (int i = 0; i < 8; i++) a[i] = As[k][ty * 8 + i];
#pragma unroll
            for (int j = 0; j < 8; j++) b[j] = Bs[k][tx * 8 + j];
#pragma unroll
            for (int i = 0; i < 8; i++)
#pragma unroll
                for (int j = 0; j < 8; j++)
                    acc[i][j] = fmaf(a[i], b[j], acc[i][j]);
        }
        __syncthreads();
    }

#pragma unroll
    for (int i = 0; i < 8; i++) {
        int r = row0 + ty * 8 + i;
        if (r >= M) continue;
#pragma unroll
        for (int j = 0; j < 8; j++) {
            int c = col0 + tx * 8 + j;
            if (c >= N) continue;
            float v = acc[i][j];
            if (bias1) v += bias1[c];
            if (bias2) v += bias2[c];
            if (do_relu) v = fmaxf(v, 0.f);
            C[(size_t)r * ldc + c] = v;
        }
    }
}

// ---------------------------------------------------------------------------
// CSR build
// ---------------------------------------------------------------------------
__global__ void zero_int_kernel(int* p, int n)
{
    int i = blockIdx.x * blockDim.x + threadIdx.x;
    if (i < n) p[i] = 0;
}

__global__ void count_kernel(const int* __restrict__ dst, int* __restrict__ deg, int e)
{
    int i = blockIdx.x * blockDim.x + threadIdx.x;
    if (i < e) atomicAdd(&deg[dst[i]], 1);
}

// single-block exclusive scan over n ints (n up to a few 100k; tiles of 1024)
__global__ void scan_kernel(const int* __restrict__ deg, int* __restrict__ rowptr, int n)
{
    __shared__ int sh[1024];
    __shared__ int carry;
    int tid = threadIdx.x;
    if (tid == 0) carry = 0;
    __syncthreads();
    for (int base = 0; base < n; base += 1024) {
        int v = (base + tid < n) ? deg[base + tid] : 0;
        sh[tid] = v;
        __syncthreads();
        for (int off = 1; off < 1024; off <<= 1) {
            int t = (tid >= off) ? sh[tid - off] : 0;
            __syncthreads();
            sh[tid] += t;
            __syncthreads();
        }
        if (base + tid < n) rowptr[base + tid] = carry + sh[tid] - v;  // exclusive
        __syncthreads();
        if (tid == 1023) carry += sh[1023];
        __syncthreads();
    }
    if (tid == 0) rowptr[n] = carry;
}

__global__ void scatter_kernel(const int* __restrict__ src, const int* __restrict__ dst,
                               const int* __restrict__ rowptr, int* __restrict__ cursor,
                               int* __restrict__ csr, int e)
{
    int i = blockIdx.x * blockDim.x + threadIdx.x;
    if (i < e) {
        int d = dst[i];
        int pos = rowptr[d] + atomicAdd(&cursor[d], 1);
        csr[pos] = src[i];
    }
}

// ---------------------------------------------------------------------------
// Per-node attention coefficients: a_src[n,h] = <xs[n,h,:], a_s[h,:]>, same for dst
// grid = NN blocks, 128 threads (warp w handles head w)
// ---------------------------------------------------------------------------
__global__ void att_kernel(const float* __restrict__ xs, const float* __restrict__ xd,
                           const float* __restrict__ as, const float* __restrict__ ad,
                           float* __restrict__ a_src, float* __restrict__ a_dst)
{
    int node = blockIdx.x;
    int w = threadIdx.x >> 5;
    int lane = threadIdx.x & 31;
    const float* xsp = xs + (size_t)node * HD + w * HID;
    const float* xdp = xd + (size_t)node * HD + w * HID;
    const float* asp = as + w * HID;
    const float* adp = ad + w * HID;
    float s1 = 0.f, s2 = 0.f;
#pragma unroll
    for (int i = 0; i < 4; i++) {
        int d = lane + i * 32;
        s1 = fmaf(xsp[d], asp[d], s1);
        s2 = fmaf(xdp[d], adp[d], s2);
    }
#pragma unroll
    for (int o = 16; o > 0; o >>= 1) {
        s1 += __shfl_xor_sync(0xffffffffu, s1, o);
        s2 += __shfl_xor_sync(0xffffffffu, s2, o);
    }
    if (lane == 0) {
        a_src[node * NHEAD + w] = s1;
        a_dst[node * NHEAD + w] = s2;
    }
}

// ---------------------------------------------------------------------------
// GAT aggregation: one warp per destination node.
// Phase 1: per-head max of leaky_relu scores; phase 2: exp-sum; phase 3: gather.
// Epilogue: out = relu(agg + lin)  (lin already includes g_b + l_b)
// ---------------------------------------------------------------------------
__device__ __forceinline__ float leaky(float v) { return v > 0.f ? v : NEG_SLOPE * v; }

__global__ void __launch_bounds__(256)
agg_kernel(const int* __restrict__ rowptr, const int* __restrict__ csr,
           const float* __restrict__ a_src, const float* __restrict__ a_dst,
           const float* __restrict__ xs, const float* __restrict__ lin,
           float* __restrict__ out)
{
    int warp = (blockIdx.x * blockDim.x + threadIdx.x) >> 5;
    int lane = threadIdx.x & 31;
    if (warp >= NN) return;
    const int node = warp;
    const int beg = rowptr[node];
    const int end = rowptr[node + 1];

    const float ad0 = a_dst[node * 4 + 0];
    const float ad1 = a_dst[node * 4 + 1];
    const float ad2 = a_dst[node * 4 + 2];
    const float ad3 = a_dst[node * 4 + 3];

    // phase 1: max per head
    float m0 = -1e30f, m1 = -1e30f, m2 = -1e30f, m3 = -1e30f;
    for (int i = beg + lane; i < end; i += 32) {
        int s = csr[i];
        const float* ap = a_src + (size_t)s * 4;
        m0 = fmaxf(m0, leaky(ap[0] + ad0));
        m1 = fmaxf(m1, leaky(ap[1] + ad1));
        m2 = fmaxf(m2, leaky(ap[2] + ad2));
        m3 = fmaxf(m3, leaky(ap[3] + ad3));
    }
#pragma unroll
    for (int o = 16; o > 0; o >>= 1) {
        m0 = fmaxf(m0, __shfl_xor_sync(0xffffffffu, m0, o));
        m1 = fmaxf(m1, __shfl_xor_sync(0xffffffffu, m1, o));
        m2 = fmaxf(m2, __shfl_xor_sync(0xffffffffu, m2, o));
        m3 = fmaxf(m3, __shfl_xor_sync(0xffffffffu, m3, o));
    }

    // phase 2: exp-sum per head
    float s0 = 0.f, s1 = 0.f, s2 = 0.f, s3 = 0.f;
    for (int i = beg + lane; i < end; i += 32) {
        int s = csr[i];
        const float* ap = a_src + (size_t)s * 4;
        s0 += expf(leaky(ap[0] + ad0) - m0);
        s1 += expf(leaky(ap[1] + ad1) - m1);
        s2 += expf(leaky(ap[2] + ad2) - m2);
        s3 += expf(leaky(ap[3] + ad3) - m3);
    }
#pragma unroll
    for (int o = 16; o > 0; o >>= 1) {
        s0 += __shfl_xor_sync(0xffffffffu, s0, o);
        s1 += __shfl_xor_sync(0xffffffffu, s1, o);
        s2 += __shfl_xor_sync(0xffffffffu, s2, o);
        s3 += __shfl_xor_sync(0xffffffffu, s3, o);
    }

    // per-lane head selection: lane handles cols [lane*16, lane*16+16) -> head = lane/8
    const int myh = lane >> 3;
    const float m_my  = (myh < 2) ? (myh == 0 ? m0 : m1) : (myh == 2 ? m2 : m3);
    const float sum_my = (myh < 2) ? (myh == 0 ? s0 : s1) : (myh == 2 ? s2 : s3);
    const float ad_my = (myh < 2) ? (myh == 0 ? ad0 : ad1) : (myh == 2 ? ad2 : ad3);
    const float inv_my = 1.f / (sum_my + 1e-16f);

    float4 acc0 = make_float4(0.f, 0.f, 0.f, 0.f);
    float4 acc1 = acc0, acc2 = acc0, acc3 = acc0;

    // phase 3: weighted gather of source projections
    for (int i = beg; i < end; i++) {
        int s = csr[i];
        float v = leaky(a_src[(size_t)s * 4 + myh] + ad_my);
        float w = expf(v - m_my) * inv_my;
        const float4* xp = (const float4*)(xs + (size_t)s * HD + lane * 16);
        float4 x0 = xp[0], x1 = xp[1], x2 = xp[2], x3 = xp[3];
        acc0.x = fmaf(w, x0.x, acc0.x); acc0.y = fmaf(w, x0.y, acc0.y);
        acc0.z = fmaf(w, x0.z, acc0.z); acc0.w = fmaf(w, x0.w, acc0.w);
        acc1.x = fmaf(w, x1.x, acc1.x); acc1.y = fmaf(w, x1.y, acc1.y);
        acc1.z = fmaf(w, x1.z, acc1.z); acc1.w = fmaf(w, x1.w, acc1.w);
        acc2.x = fmaf(w, x2.x, acc2.x); acc2.y = fmaf(w, x2.y, acc2.y);
        acc2.z = fmaf(w, x2.z, acc2.z); acc2.w = fmaf(w, x2.w, acc2.w);
        acc3.x = fmaf(w, x3.x, acc3.x); acc3.y = fmaf(w, x3.y, acc3.y);
        acc3.z = fmaf(w, x3.z, acc3.z); acc3.w = fmaf(w, x3.w, acc3.w);
    }

    // epilogue: relu(agg + lin)
    const float4* lp = (const float4*)(lin + (size_t)node * HD + lane * 16);
    float4* op = (float4*)(out + (size_t)node * HD + lane * 16);
    float4 l0 = lp[0], l1 = lp[1], l2 = lp[2], l3 = lp[3];
    float4 r0, r1, r2, r3;
    r0.x = fmaxf(acc0.x + l0.x, 0.f); r0.y = fmaxf(acc0.y + l0.y, 0.f);
    r0.z = fmaxf(acc0.z + l0.z, 0.f); r0.w = fmaxf(acc0.w + l0.w, 0.f);
    r1.x = fmaxf(acc1.x + l1.x, 0.f); r1.y = fmaxf(acc1.y + l1.y, 0.f);
    r1.z = fmaxf(acc1.z + l1.z, 0.f); r1.w = fmaxf(acc1.w + l1.w, 0.f);
    r2.x = fmaxf(acc2.x + l2.x, 0.f); r2.y = fmaxf(acc2.y + l2.y, 0.f);
    r2.z = fmaxf(acc2.z + l2.z, 0.f); r2.w = fmaxf(acc2.w + l2.w, 0.f);
    r3.x = fmaxf(acc3.x + l3.x, 0.f); r3.y = fmaxf(acc3.y + l3.y, 0.f);
    r3.z = fmaxf(acc3.z + l3.z, 0.f); r3.w = fmaxf(acc3.w + l3.w, 0.f);
    op[0] = r0; op[1] = r1; op[2] = r2; op[3] = r3;
}

// ---------------------------------------------------------------------------
// Host side
// ---------------------------------------------------------------------------
static void gemm(const float* A, int lda, const float* B, int ldb,
                 float* C, int ldc, int M, int N, int K,
                 const float* b1, const float* b2, bool relu)
{
    dim3 grid((N + TN - 1) / TN, (M + TM - 1) / TM);
    sgemm_kernel<<<grid, 256>>>(A, lda, B, ldb, C, ldc, M, N, K, b1, b2, relu ? 1 : 0);
}

extern "C" void kernel_launch(void* const* d_in, const int* in_sizes, int n_in,
                              void* d_out, int out_size)
{
    const float* x      = (const float*)d_in[0];
    const int*   ei     = (const int*)d_in[1];
    const float* W_rna  = (const float*)d_in[2];
    const float* b_rna  = (const float*)d_in[3];
    const float* W_prot = (const float*)d_in[4];
    const float* b_prot = (const float*)d_in[5];
    const float* g1_ws  = (const float*)d_in[6];
    const float* g1_wd  = (const float*)d_in[7];
    const float* g1_as  = (const float*)d_in[8];
    const float* g1_ad  = (const float*)d_in[9];
    const float* g1_b   = (const float*)d_in[10];
    const float* l1_w   = (const float*)d_in[11];
    const float* l1_b   = (const float*)d_in[12];
    const float* g2_ws  = (const float*)d_in[13];
    const float* g2_wd  = (const float*)d_in[14];
    const float* g2_as  = (const float*)d_in[15];
    const float* g2_ad  = (const float*)d_in[16];
    const float* g2_b   = (const float*)d_in[17];
    const float* l2_w   = (const float*)d_in[18];
    const float* l2_b   = (const float*)d_in[19];
    const float* agg_w  = (const float*)d_in[20];
    const float* agg_b  = (const float*)d_in[21];
    const float* dr_w   = (const float*)d_in[22];
    const float* dr_b   = (const float*)d_in[23];
    const float* dp_w   = (const float*)d_in[24];
    const float* dp_b   = (const float*)d_in[25];
    const float* rr_w   = (const float*)d_in[26];
    const float* rr_b   = (const float*)d_in[27];
    const float* rp_w   = (const float*)d_in[28];
    const float* rp_b   = (const float*)d_in[29];

    float* out = (float*)d_out;
    float* out_rna  = out;                                   // [N, RNA]
    float* out_prot = out + (size_t)NN * RNA;                // [N, PROT]
    float* out_emb  = out + (size_t)NN * (RNA + PROT);       // [N, HID]

    float *h0, *h1, *xs, *xd, *lin, *asrc, *adst;
    int *deg, *cur, *rowptr, *csr;
    cudaGetSymbolAddress((void**)&h0,   g_h0);
    cudaGetSymbolAddress((void**)&h1,   g_h1);
    cudaGetSymbolAddress((void**)&xs,   g_xs);
    cudaGetSymbolAddress((void**)&xd,   g_xd);
    cudaGetSymbolAddress((void**)&lin,  g_lin);
    cudaGetSymbolAddress((void**)&asrc, g_asrc);
    cudaGetSymbolAddress((void**)&adst, g_adst);
    cudaGetSymbolAddress((void**)&deg,    g_deg);
    cudaGetSymbolAddress((void**)&cur,    g_cursor);
    cudaGetSymbolAddress((void**)&rowptr, g_rowptr);
    cudaGetSymbolAddress((void**)&csr,    g_csr);

    const int* e_src = ei;
    const int* e_dst = ei + EE;

    // ---- CSR build (edges grouped by destination) ----
    int nbN = (NN + 255) / 256;
    int nbE = (EE + 255) / 256;
    zero_int_kernel<<<nbN, 256>>>(deg, NN);
    zero_int_kernel<<<nbN, 256>>>(cur, NN);
    count_kernel<<<nbE, 256>>>(e_dst, deg, EE);
    scan_kernel<<<1, 1024>>>(deg, rowptr, NN);
    scatter_kernel<<<nbE, 256>>>(e_src, e_dst, rowptr, cur, csr, EE);

    // ---- input embeddings: h0 = [rna_e | prot_e] ----
    gemm(x,        INF, W_rna,  EMB, h0,        HD, NN, EMB, RNA,  b_rna,  nullptr, false);
    gemm(x + RNA,  INF, W_prot, EMB, h0 + EMB,  HD, NN, EMB, PROT, b_prot, nullptr, false);

    // ---- GAT layer 1 (in h0 -> out h1) ----
    gemm(h0, HD, g1_ws, HD, xs,  HD, NN, HD, HD, nullptr, nullptr, false);
    gemm(h0, HD, g1_wd, HD, xd,  HD, NN, HD, HD, nullptr, nullptr, false);
    gemm(h0, HD, l1_w,  HD, lin, HD, NN, HD, HD, l1_b,    g1_b,    false);
    att_kernel<<<NN, 128>>>(xs, xd, g1_as, g1_ad, asrc, adst);
    agg_kernel<<<(NN * 32 + 255) / 256, 256>>>(rowptr, csr, asrc, adst, xs, lin, h1);

    // ---- GAT layer 2 (in h1 -> out h0) ----
    gemm(h1, HD, g2_ws, HD, xs,  HD, NN, HD, HD, nullptr, nullptr, false);
    gemm(h1, HD, g2_wd, HD, xd,  HD, NN, HD, HD, nullptr, nullptr, false);
    gemm(h1, HD, l2_w,  HD, lin, HD, NN, HD, HD, l2_b,    g2_b,    false);
    att_kernel<<<NN, 128>>>(xs, xd, g2_as, g2_ad, asrc, adst);
    agg_kernel<<<(NN * 32 + 255) / 256, 256>>>(rowptr, csr, asrc, adst, xs, lin, h0);

    // ---- head ----
    // embedding = relu(h0 @ agg_w + agg_b) -> directly into output
    gemm(h0, HD, agg_w, HID, out_emb, HID, NN, HID, HD, agg_b, nullptr, true);
    // decoders (reuse xs/xd as scratch)
    gemm(out_emb, HID, dr_w, EMB, xs, EMB, NN, EMB, HID, dr_b, nullptr, false);
    gemm(out_emb, HID, dp_w, EMB, xd, EMB, NN, EMB, HID, dp_b, nullptr, false);
    // reconstructions
    gemm(xs, EMB, rr_w, RNA,  out_rna,  RNA,  NN, RNA,  EMB, rr_b, nullptr, false);
    gemm(xd, EMB, rp_w, PROT, out_prot, PROT, NN, PROT, EMB, rp_b, nullptr, false);
}